// round 1
// baseline (speedup 1.0000x reference)
#include <cuda_runtime.h>
#include <cuda_bf16.h>

#define N_NODES 50000
#define N_EDGES 800000
#define IN_DIM  128
#define OUT_DIM 64

// scratch for hidden = x @ w   (12.8 MB, static device array — allowed)
__device__ float g_hidden[N_NODES * OUT_DIM];

// ---------------------------------------------------------------------------
// Kernel 1: out[i, j] = b[j]   (bias init; accumulation target)
// ---------------------------------------------------------------------------
__global__ void init_bias_kernel(float* __restrict__ out, const float* __restrict__ b) {
    int i = blockIdx.x * blockDim.x + threadIdx.x;
    int total = N_NODES * OUT_DIM;
    if (i < total) {
        out[i] = b[i & (OUT_DIM - 1)];
    }
}

// ---------------------------------------------------------------------------
// Kernel 2: hidden = x @ w
// Block: 256 threads -> 4 rows x 64 cols. w (32 KB) staged in smem,
// x rows (4x128 floats) staged in smem.
// ---------------------------------------------------------------------------
__global__ void gemm_kernel(const float* __restrict__ x, const float* __restrict__ w) {
    __shared__ float ws[IN_DIM * OUT_DIM];   // 32 KB
    __shared__ float xs[4 * IN_DIM];         // 2 KB

    int tid = threadIdx.x;

    // load w cooperatively (8192 floats / 256 threads = 32 each)
    #pragma unroll
    for (int i = 0; i < (IN_DIM * OUT_DIM) / 256; i++) {
        ws[tid + i * 256] = w[tid + i * 256];
    }

    int row_base = blockIdx.x * 4;
    // load 4 x-rows (512 floats / 256 threads = 2 each)
    #pragma unroll
    for (int i = 0; i < 2; i++) {
        int idx = tid + i * 256;          // 0..511
        int r = idx >> 7;                 // 0..3
        int k = idx & (IN_DIM - 1);
        int grow = row_base + r;
        xs[idx] = (grow < N_NODES) ? x[grow * IN_DIM + k] : 0.0f;
    }
    __syncthreads();

    int col = tid & (OUT_DIM - 1);
    int r   = tid >> 6;                   // 0..3
    int grow = row_base + r;
    if (grow >= N_NODES) return;

    float acc = 0.0f;
    #pragma unroll 8
    for (int k = 0; k < IN_DIM; k++) {
        acc = fmaf(xs[r * IN_DIM + k], ws[k * OUT_DIM + col], acc);
    }
    g_hidden[grow * OUT_DIM + col] = acc;
}

// ---------------------------------------------------------------------------
// Kernel 3: edge scatter. One warp per edge; lane handles 2 columns (float2
// gather from hidden, two scalar fp32 atomic adds into out).
// ---------------------------------------------------------------------------
__global__ void scatter_kernel(const int* __restrict__ edge_row,
                               const int* __restrict__ edge_col,
                               const float* __restrict__ edge_val,
                               float* __restrict__ out) {
    int warp_id = (blockIdx.x * blockDim.x + threadIdx.x) >> 5;
    int lane = threadIdx.x & 31;
    if (warp_id >= N_EDGES) return;

    int   row = edge_row[warp_id];   // broadcast load across the warp
    int   col = edge_col[warp_id];
    float val = edge_val[warp_id];

    const float2* hsrc = reinterpret_cast<const float2*>(g_hidden + (size_t)col * OUT_DIM);
    float2 h = hsrc[lane];

    float* dst = out + (size_t)row * OUT_DIM + lane * 2;
    atomicAdd(dst + 0, val * h.x);
    atomicAdd(dst + 1, val * h.y);
}

// ---------------------------------------------------------------------------
// Kernel 4: in-place ReLU
// ---------------------------------------------------------------------------
__global__ void relu_kernel(float* __restrict__ out) {
    int i = blockIdx.x * blockDim.x + threadIdx.x;
    int total = N_NODES * OUT_DIM;
    if (i < total) {
        float v = out[i];
        out[i] = v > 0.0f ? v : 0.0f;
    }
}

// ---------------------------------------------------------------------------
extern "C" void kernel_launch(void* const* d_in, const int* in_sizes, int n_in,
                              void* d_out, int out_size) {
    const float* x        = (const float*)d_in[0];
    const int*   edge_row = (const int*)  d_in[1];
    const int*   edge_col = (const int*)  d_in[2];
    const float* edge_val = (const float*)d_in[3];
    const float* w        = (const float*)d_in[4];
    const float* b        = (const float*)d_in[5];
    float* out = (float*)d_out;

    int total = N_NODES * OUT_DIM;

    init_bias_kernel<<<(total + 255) / 256, 256>>>(out, b);
    gemm_kernel<<<(N_NODES + 3) / 4, 256>>>(x, w);
    // 8 warps per block -> 8 edges per block
    scatter_kernel<<<(N_EDGES + 7) / 8, 256>>>(edge_row, edge_col, edge_val, out);
    relu_kernel<<<(total + 255) / 256, 256>>>(out);
}

// round 2
// speedup vs baseline: 1.9505x; 1.9505x over previous
#include <cuda_runtime.h>
#include <cuda_bf16.h>

#define N_NODES 50000
#define N_EDGES 800000
#define IN_DIM  128
#define OUT_DIM 64

// scratch for hidden = x @ w   (12.8 MB, static device array — allowed)
__device__ float g_hidden[N_NODES * OUT_DIM];

// ---------------------------------------------------------------------------
// Kernel 1: out[i, j] = b[j]   (bias init; accumulation target), float4 writes
// ---------------------------------------------------------------------------
__global__ void init_bias_kernel(float4* __restrict__ out, const float4* __restrict__ b4) {
    int i = blockIdx.x * blockDim.x + threadIdx.x;       // float4 index
    int total4 = (N_NODES * OUT_DIM) / 4;
    if (i < total4) {
        out[i] = b4[i & (OUT_DIM / 4 - 1)];
    }
}

// ---------------------------------------------------------------------------
// Kernel 2: hidden = x @ w
// Block: 256 threads -> 16 rows x 64 cols (4 rows per thread).
// w (32 KB) staged once per block; x rows staged via float4.
// ---------------------------------------------------------------------------
#define GEMM_ROWS 16
__global__ void gemm_kernel(const float* __restrict__ x, const float* __restrict__ w) {
    __shared__ float ws[IN_DIM * OUT_DIM];            // 32 KB
    __shared__ float xs[GEMM_ROWS * IN_DIM];          // 8 KB

    int tid = threadIdx.x;

    // load w cooperatively (8192 floats / 256 threads = 32 each, float4)
    {
        const float4* w4 = reinterpret_cast<const float4*>(w);
        float4* ws4 = reinterpret_cast<float4*>(ws);
        #pragma unroll
        for (int i = 0; i < (IN_DIM * OUT_DIM) / 4 / 256; i++) {
            ws4[tid + i * 256] = w4[tid + i * 256];
        }
    }

    int row_base = blockIdx.x * GEMM_ROWS;
    // load 16 x-rows = 2048 floats = 512 float4 / 256 threads = 2 each
    {
        float4* xs4 = reinterpret_cast<float4*>(xs);
        const float4* x4 = reinterpret_cast<const float4*>(x);
        #pragma unroll
        for (int i = 0; i < 2; i++) {
            int idx = tid + i * 256;                  // float4 index within tile
            int r = idx / (IN_DIM / 4);
            int k4 = idx & (IN_DIM / 4 - 1);
            int grow = row_base + r;
            xs4[idx] = (grow < N_NODES) ? x4[(size_t)grow * (IN_DIM / 4) + k4]
                                        : make_float4(0.f, 0.f, 0.f, 0.f);
        }
    }
    __syncthreads();

    int col = tid & (OUT_DIM - 1);
    int r0  = (tid >> 6) * 4;                         // 0,4,8,12

    float acc0 = 0.f, acc1 = 0.f, acc2 = 0.f, acc3 = 0.f;
    #pragma unroll 4
    for (int k = 0; k < IN_DIM; k++) {
        float wv = ws[k * OUT_DIM + col];
        acc0 = fmaf(xs[(r0 + 0) * IN_DIM + k], wv, acc0);
        acc1 = fmaf(xs[(r0 + 1) * IN_DIM + k], wv, acc1);
        acc2 = fmaf(xs[(r0 + 2) * IN_DIM + k], wv, acc2);
        acc3 = fmaf(xs[(r0 + 3) * IN_DIM + k], wv, acc3);
    }
    int grow = row_base + r0;
    if (grow + 0 < N_NODES) g_hidden[(size_t)(grow + 0) * OUT_DIM + col] = acc0;
    if (grow + 1 < N_NODES) g_hidden[(size_t)(grow + 1) * OUT_DIM + col] = acc1;
    if (grow + 2 < N_NODES) g_hidden[(size_t)(grow + 2) * OUT_DIM + col] = acc2;
    if (grow + 3 < N_NODES) g_hidden[(size_t)(grow + 3) * OUT_DIM + col] = acc3;
}

// ---------------------------------------------------------------------------
// Kernel 3: edge scatter with VECTOR float4 atomics (sm_90+ RED.ADD.F32X4).
// 16 lanes per edge; each lane: one float4 gather + one float4 atomicAdd.
// ---------------------------------------------------------------------------
__global__ void scatter_kernel(const int* __restrict__ edge_row,
                               const int* __restrict__ edge_col,
                               const float* __restrict__ edge_val,
                               float* __restrict__ out) {
    int gid  = blockIdx.x * blockDim.x + threadIdx.x;
    int edge = gid >> 4;                  // 16 lanes per edge
    int lane = gid & 15;
    if (edge >= N_EDGES) return;

    int   row = edge_row[edge];
    int   col = edge_col[edge];
    float val = edge_val[edge];

    const float4* hsrc = reinterpret_cast<const float4*>(g_hidden + (size_t)col * OUT_DIM);
    float4 h = hsrc[lane];

    float4 m = make_float4(val * h.x, val * h.y, val * h.z, val * h.w);
    float4* dst = reinterpret_cast<float4*>(out + (size_t)row * OUT_DIM) + lane;
    atomicAdd(dst, m);                    // RED.E.ADD.F32X4 (return discarded)
}

// ---------------------------------------------------------------------------
// Kernel 4: in-place ReLU, float4
// ---------------------------------------------------------------------------
__global__ void relu_kernel(float4* __restrict__ out) {
    int i = blockIdx.x * blockDim.x + threadIdx.x;
    int total4 = (N_NODES * OUT_DIM) / 4;
    if (i < total4) {
        float4 v = out[i];
        v.x = fmaxf(v.x, 0.f);
        v.y = fmaxf(v.y, 0.f);
        v.z = fmaxf(v.z, 0.f);
        v.w = fmaxf(v.w, 0.f);
        out[i] = v;
    }
}

// ---------------------------------------------------------------------------
extern "C" void kernel_launch(void* const* d_in, const int* in_sizes, int n_in,
                              void* d_out, int out_size) {
    const float* x        = (const float*)d_in[0];
    const int*   edge_row = (const int*)  d_in[1];
    const int*   edge_col = (const int*)  d_in[2];
    const float* edge_val = (const float*)d_in[3];
    const float* w        = (const float*)d_in[4];
    const float* b        = (const float*)d_in[5];
    float* out = (float*)d_out;

    int total4 = (N_NODES * OUT_DIM) / 4;

    init_bias_kernel<<<(total4 + 255) / 256, 256>>>(
        (float4*)out, (const float4*)b);
    gemm_kernel<<<(N_NODES + GEMM_ROWS - 1) / GEMM_ROWS, 256>>>(x, w);
    // 16 lanes/edge, 256 threads/block -> 16 edges per block
    scatter_kernel<<<(N_EDGES * 16 + 255) / 256, 256>>>(edge_row, edge_col, edge_val, out);
    relu_kernel<<<(total4 + 255) / 256, 256>>>((float4*)out);
}

// round 4
// speedup vs baseline: 2.3858x; 1.2232x over previous
#include <cuda_runtime.h>
#include <cuda_bf16.h>
#include <cstdint>

#define N_NODES 50000
#define N_EDGES 800000
#define IN_DIM  128
#define OUT_DIM 64

// scratch for hidden = x @ w   (12.8 MB, static device array — allowed)
__device__ float g_hidden[N_NODES * OUT_DIM];

// ---------------------------------------------------------------------------
// packed f32x2 helpers
// ---------------------------------------------------------------------------
__device__ __forceinline__ unsigned long long dup2(float v) {
    unsigned long long r;
    asm("mov.b64 %0, {%1, %1};" : "=l"(r) : "f"(v));
    return r;
}
#define FMA2(acc, a, b) \
    asm("fma.rn.f32x2 %0, %1, %2, %0;" : "+l"(acc) : "l"(a), "l"(b))

// ---------------------------------------------------------------------------
// Kernel 1: out[i, j] = b[j]   (bias init), float4 writes
// ---------------------------------------------------------------------------
__global__ void init_bias_kernel(float4* __restrict__ out, const float4* __restrict__ b4) {
    int i = blockIdx.x * blockDim.x + threadIdx.x;
    int total4 = (N_NODES * OUT_DIM) / 4;
    if (i < total4) {
        out[i] = b4[i & (OUT_DIM / 4 - 1)];
    }
}

// ---------------------------------------------------------------------------
// Kernel 2: hidden = x @ w  — register-tiled, packed f32x2 FMA.
// 128 threads = 4 warps; block tile = 128 rows x 64 cols.
// Thread tile: 8 rows x 8 cols (8x4 f32x2 accumulators).
// Lane map: pg = lane&7 -> cols [pg*8, pg*8+8); rg = lane>>3 -> row group.
// Thread rows: warp*32 + rg*8 + j, j=0..7.
//
// xs skew (MONOTONIC, fixes R3 overlap bug):
//   XROW(r) = r*128 + ((r>>3)&3)*4 + (r>>5)*16
// - strictly increasing by >=128 words per row (no overlap; 32-boundary step
//   is 128 - 12 + 16 = +132)
// - within one warp (rows warp*32 .. +31) the (r>>5) term is constant, so the
//   4 rg-broadcast addresses at fixed k differ by 1028 mod 32 = 4 words ->
//   banks {b, b+4, b+8, b+12}: conflict-free broadcast
// - XROW % 4 == 0 -> float4 staging stays 16B-aligned
// ---------------------------------------------------------------------------
#define GEMM_ROWS 128
#define GEMM_THREADS 128
#define XROW(r) ((r) * IN_DIM + ((((r) >> 3) & 3) << 2) + (((r) >> 5) << 4))
#define XS_FLOATS (XROW(GEMM_ROWS - 1) + IN_DIM + 16)
#define WS_FLOATS (IN_DIM * OUT_DIM)
#define GEMM_SMEM_BYTES ((WS_FLOATS + XS_FLOATS) * 4)

__global__ void __launch_bounds__(GEMM_THREADS)
gemm_kernel(const float* __restrict__ x, const float* __restrict__ w) {
    extern __shared__ float smem[];
    float* ws = smem;                    // [128][64]
    float* xs = smem + WS_FLOATS;        // skewed [128][128]

    int tid  = threadIdx.x;
    int warp = tid >> 5;
    int lane = tid & 31;
    int pg   = lane & 7;
    int rg   = lane >> 3;
    int bb   = blockIdx.x * GEMM_ROWS;

    // ---- stage w (2048 float4, 16 per thread)
    {
        const float4* w4 = reinterpret_cast<const float4*>(w);
        float4* ws4 = reinterpret_cast<float4*>(ws);
        #pragma unroll
        for (int i = 0; i < WS_FLOATS / 4 / GEMM_THREADS; i++) {
            int c = i * GEMM_THREADS + tid;
            ws4[c] = w4[c];
        }
    }
    // ---- stage x tile (128 rows x 32 float4)
    {
        const float4* x4 = reinterpret_cast<const float4*>(x);
        #pragma unroll
        for (int i = 0; i < (GEMM_ROWS * IN_DIM / 4) / GEMM_THREADS; i++) {
            int c  = i * GEMM_THREADS + tid;
            int r  = c >> 5;                 // local row
            int k4 = c & 31;                 // float4 within row
            int grow = bb + r;
            float4 v = (grow < N_NODES) ? x4[(size_t)grow * (IN_DIM / 4) + k4]
                                        : make_float4(0.f, 0.f, 0.f, 0.f);
            *reinterpret_cast<float4*>(&xs[XROW(r) + k4 * 4]) = v;
        }
    }
    __syncthreads();

    // ---- main loop
    unsigned long long acc[8][4];
    #pragma unroll
    for (int j = 0; j < 8; j++)
        #pragma unroll
        for (int p = 0; p < 4; p++) acc[j][p] = 0ull;

    int wrb = warp * 32 + rg * 8;        // first local row of this thread
    uint32_t ws_base = (uint32_t)__cvta_generic_to_shared(ws) + (uint32_t)(pg * 32);
    // rows wrb..wrb+7 share both skew terms (same rg group, same r>>5):
    // xs addr of (wrb+j, k) == xrow0 + j*IN_DIM + k
    const float* xrow0 = xs + XROW(wrb);

    #pragma unroll 4
    for (int k = 0; k < IN_DIM; k++) {
        // 8 w-cols at row k: 32 bytes = 2 x ld.shared.v2.b64
        unsigned long long wpa, wpb, wpc, wpd;
        uint32_t wa = ws_base + (uint32_t)(k * (OUT_DIM * 4));
        asm("ld.shared.v2.b64 {%0, %1}, [%2];" : "=l"(wpa), "=l"(wpb) : "r"(wa));
        asm("ld.shared.v2.b64 {%0, %1}, [%2];" : "=l"(wpc), "=l"(wpd) : "r"(wa + 16));

        #pragma unroll
        for (int j = 0; j < 8; j++) {
            unsigned long long xp = dup2(xrow0[j * IN_DIM + k]);
            FMA2(acc[j][0], xp, wpa);
            FMA2(acc[j][1], xp, wpb);
            FMA2(acc[j][2], xp, wpc);
            FMA2(acc[j][3], xp, wpd);
        }
    }

    // ---- epilogue: 8 rows x 8 cols, two float4 stores per row
    #pragma unroll
    for (int j = 0; j < 8; j++) {
        int grow = bb + wrb + j;
        if (grow < N_NODES) {
            float2 a0 = *reinterpret_cast<float2*>(&acc[j][0]);
            float2 a1 = *reinterpret_cast<float2*>(&acc[j][1]);
            float2 a2 = *reinterpret_cast<float2*>(&acc[j][2]);
            float2 a3 = *reinterpret_cast<float2*>(&acc[j][3]);
            float4* dst = reinterpret_cast<float4*>(g_hidden + (size_t)grow * OUT_DIM + pg * 8);
            dst[0] = make_float4(a0.x, a0.y, a1.x, a1.y);
            dst[1] = make_float4(a2.x, a2.y, a3.x, a3.y);
        }
    }
}

// ---------------------------------------------------------------------------
// Kernel 3: edge scatter with VECTOR float4 atomics (RED.ADD.F32X4).
// ---------------------------------------------------------------------------
__global__ void scatter_kernel(const int* __restrict__ edge_row,
                               const int* __restrict__ edge_col,
                               const float* __restrict__ edge_val,
                               float* __restrict__ out) {
    int gid  = blockIdx.x * blockDim.x + threadIdx.x;
    int edge = gid >> 4;                  // 16 lanes per edge
    int lane = gid & 15;
    if (edge >= N_EDGES) return;

    int   row = edge_row[edge];
    int   col = edge_col[edge];
    float val = edge_val[edge];

    const float4* hsrc = reinterpret_cast<const float4*>(g_hidden + (size_t)col * OUT_DIM);
    float4 h = hsrc[lane];

    float4 m = make_float4(val * h.x, val * h.y, val * h.z, val * h.w);
    float4* dst = reinterpret_cast<float4*>(out + (size_t)row * OUT_DIM) + lane;
    atomicAdd(dst, m);
}

// ---------------------------------------------------------------------------
// Kernel 4: in-place ReLU, float4
// ---------------------------------------------------------------------------
__global__ void relu_kernel(float4* __restrict__ out) {
    int i = blockIdx.x * blockDim.x + threadIdx.x;
    int total4 = (N_NODES * OUT_DIM) / 4;
    if (i < total4) {
        float4 v = out[i];
        v.x = fmaxf(v.x, 0.f);
        v.y = fmaxf(v.y, 0.f);
        v.z = fmaxf(v.z, 0.f);
        v.w = fmaxf(v.w, 0.f);
        out[i] = v;
    }
}

// ---------------------------------------------------------------------------
extern "C" void kernel_launch(void* const* d_in, const int* in_sizes, int n_in,
                              void* d_out, int out_size) {
    const float* x        = (const float*)d_in[0];
    const int*   edge_row = (const int*)  d_in[1];
    const int*   edge_col = (const int*)  d_in[2];
    const float* edge_val = (const float*)d_in[3];
    const float* w        = (const float*)d_in[4];
    const float* b        = (const float*)d_in[5];
    float* out = (float*)d_out;

    int total4 = (N_NODES * OUT_DIM) / 4;

    cudaFuncSetAttribute(gemm_kernel,
                         cudaFuncAttributeMaxDynamicSharedMemorySize,
                         GEMM_SMEM_BYTES);

    init_bias_kernel<<<(total4 + 255) / 256, 256>>>(
        (float4*)out, (const float4*)b);
    gemm_kernel<<<(N_NODES + GEMM_ROWS - 1) / GEMM_ROWS, GEMM_THREADS,
                  GEMM_SMEM_BYTES>>>(x, w);
    scatter_kernel<<<(N_EDGES * 16 + 255) / 256, 256>>>(edge_row, edge_col, edge_val, out);
    relu_kernel<<<(total4 + 255) / 256, 256>>>((float4*)out);
}